// round 16
// baseline (speedup 1.0000x reference)
#include <cuda_runtime.h>
#include <cuda_fp16.h>
#include <math.h>
#include <cstdint>

#define BB 2
#define TT 2048
#define DD 1024
#define NH 16
#define HD 64
#define LOG2E_ 1.442695041f

// ---------------------------------------------------------------------------
// Scratch (__device__ globals, allocation-free rule)
// ---------------------------------------------------------------------------
__device__ __half g_xhi[4194304], g_xlo[4194304];        // X split       [4096][1024]
__device__ __half g_wthi[3145728], g_wtlo[3145728];      // wq/wk/wv^T    [3][1024 n][1024 k]
__device__ __half g_wohi[1048576], g_wolo[1048576];      // wo split      [1024 d][1024 k]
__device__ __half g_qhi[4194304], g_qlo[4194304];        // q (scaled)    [4096][1024]
__device__ __half g_khi[4194304], g_klo[4194304];        // k             [4096][1024]
__device__ __half g_v16[4194304];                        // v fp16        [4096][1024]
__device__ __half g_ahi[4194304];                        // attn out hi   [4096][1024]
// mask packed in fragment order: [b][row][st][l(4)][j(8)][p(2)] (8MB)
__device__ unsigned char g_mask8[8388608];

// ---------------------------------------------------------------------------
// PTX helpers
// ---------------------------------------------------------------------------
__device__ __forceinline__ uint32_t smem_u32(const void* p) {
    uint32_t a;
    asm("{ .reg .u64 t; cvta.to.shared.u64 t, %1; cvt.u32.u64 %0, t; }" : "=r"(a) : "l"(p));
    return a;
}
__device__ __forceinline__ void ldsm_x4(uint32_t* r, uint32_t a) {
    asm volatile("ldmatrix.sync.aligned.m8n8.x4.shared.b16 {%0,%1,%2,%3}, [%4];"
                 : "=r"(r[0]), "=r"(r[1]), "=r"(r[2]), "=r"(r[3]) : "r"(a));
}
__device__ __forceinline__ void ldsm_x4_t(uint32_t* r, uint32_t a) {
    asm volatile("ldmatrix.sync.aligned.m8n8.x4.trans.shared.b16 {%0,%1,%2,%3}, [%4];"
                 : "=r"(r[0]), "=r"(r[1]), "=r"(r[2]), "=r"(r[3]) : "r"(a));
}
__device__ __forceinline__ void mma16816(float* c, const uint32_t* a, uint32_t b0, uint32_t b1) {
    asm volatile(
        "mma.sync.aligned.m16n8k16.row.col.f32.f16.f16.f32 "
        "{%0,%1,%2,%3}, {%4,%5,%6,%7}, {%8,%9}, {%0,%1,%2,%3};"
        : "+f"(c[0]), "+f"(c[1]), "+f"(c[2]), "+f"(c[3])
        : "r"(a[0]), "r"(a[1]), "r"(a[2]), "r"(a[3]), "r"(b0), "r"(b1));
}
#define CP_A16(dst, src) \
    asm volatile("cp.async.cg.shared.global [%0], [%1], 16;" :: "r"(dst), "l"(src))
#define CP_COMMIT() asm volatile("cp.async.commit_group;" ::: "memory")
#define CP_WAIT0()  asm volatile("cp.async.wait_group 0;" ::: "memory")

__device__ __forceinline__ float ex2(float x) {
    float y;
    asm("ex2.approx.ftz.f32 %0, %1;" : "=f"(y) : "f"(x));
    return y;
}
// two exponentials in one MUFU op; result is a packed fp16x2 (lo, hi)
__device__ __forceinline__ uint32_t ex2h2(float lo, float hi) {
    uint32_t h;
    asm("cvt.rn.f16x2.f32 %0, %1, %2;" : "=r"(h) : "f"(hi), "f"(lo));
    asm("ex2.approx.f16x2 %0, %0;" : "+r"(h));
    return h;
}

// swizzled byte offset, 64-half (128B) rows
__device__ __forceinline__ uint32_t swz_h(int r, int k) {
    return (uint32_t)(r * 128 + (((k >> 3) ^ (r & 7)) << 4) + ((k & 7) << 1));
}
__device__ __forceinline__ uint32_t pack_h2(__half a, __half b) {
    __half2 h = __halves2half2(a, b);
    return *(uint32_t*)&h;
}
__device__ __forceinline__ void split2(float x, float y, uint32_t& hi, uint32_t& lo) {
    __half hx = __float2half_rn(x), hy = __float2half_rn(y);
    hi = pack_h2(hx, hy);
    lo = pack_h2(__float2half_rn(x - __half2float(hx)),
                 __float2half_rn(y - __half2float(hy)));
}

// ---------------------------------------------------------------------------
// X split (must finish before qkv GEMM). 4096 blocks x 256.
// ---------------------------------------------------------------------------
__global__ __launch_bounds__(256) void split_x_kernel(const float* __restrict__ x)
{
    int i = blockIdx.x * 256 + threadIdx.x;
    float4 v = *(const float4*)&x[(size_t)i * 4];
    uint32_t h0, l0, h1, l1;
    split2(v.x, v.y, h0, l0);
    split2(v.z, v.w, h1, l1);
    *(uint32_t*)&g_xhi[(size_t)i * 4] = h0; *(uint32_t*)&g_xhi[(size_t)i * 4 + 2] = h1;
    *(uint32_t*)&g_xlo[(size_t)i * 4] = l0; *(uint32_t*)&g_xlo[(size_t)i * 4 + 2] = l1;
}

__global__ __launch_bounds__(256) void transpose_split_kernel(
    const float* __restrict__ wq, const float* __restrict__ wk, const float* __restrict__ wv)
{
    __shared__ float t[32][33];
    const int z = blockIdx.z;
    const float* src = (z == 0) ? wq : (z == 1) ? wk : wv;
    __half* dhi = g_wthi + (size_t)z * 1048576;
    __half* dlo = g_wtlo + (size_t)z * 1048576;
    const int tx = threadIdx.x, ty = threadIdx.y;
    const int x0 = blockIdx.x * 32;  // k
    const int y0 = blockIdx.y * 32;  // n
#pragma unroll
    for (int i = 0; i < 4; ++i)
        t[ty + i * 8][tx] = src[(size_t)(x0 + ty + i * 8) * 1024 + y0 + tx];
    __syncthreads();
#pragma unroll
    for (int i = 0; i < 4; ++i) {
        float v = t[tx][ty + i * 8];
        __half h = __float2half_rn(v);
        dhi[(size_t)(y0 + ty + i * 8) * 1024 + x0 + tx] = h;
        dlo[(size_t)(y0 + ty + i * 8) * 1024 + x0 + tx] =
            __float2half_rn(v - __half2float(h));
    }
}

// ---------------------------------------------------------------------------
// Split-fp16 HMMA GEMM (R15 config, unchanged): C = A @ B^T + bias.
// 2-stage ring, one sync per chunk; z==3 aux slice on the qkv launch.
// ---------------------------------------------------------------------------
#define G_STAGE 32768              // A 16KB + B 16KB per stage
#define GEMM_SMEM (2 * G_STAGE)    // 65536
__global__ __launch_bounds__(256, 2) void gemm_split_kernel(
    const float* __restrict__ bq, const float* __restrict__ bk,
    const float* __restrict__ bv, const float* __restrict__ bo,
    const float* __restrict__ pds, const float* __restrict__ wo,
    const int* __restrict__ msk, float* __restrict__ out, int mode_base)
{
    extern __shared__ char smem[];

    // ---- AUX slice (qkv launch only): wo split + mask packing ----
    if (mode_base == 0 && blockIdx.z == 3) {
        int t0 = (blockIdx.y * 8 + blockIdx.x) * 256 + threadIdx.x;  // 0..65535
        for (int i = t0; i < 262144; i += 65536) {                   // wo: 262144 float4
            float4 v = *(const float4*)&wo[(size_t)i * 4];
            uint32_t h0, l0, h1, l1;
            split2(v.x, v.y, h0, l0);
            split2(v.z, v.w, h1, l1);
            *(uint32_t*)&g_wohi[(size_t)i * 4] = h0; *(uint32_t*)&g_wohi[(size_t)i * 4 + 2] = h1;
            *(uint32_t*)&g_wolo[(size_t)i * 4] = l0; *(uint32_t*)&g_wolo[(size_t)i * 4 + 2] = l1;
        }
        for (int i = t0; i < 2097152; i += 65536) {                  // mask: 2097152 int4
            size_t L = (size_t)i * 4;
            int4 v = *(const int4*)&msk[L];
            int c   = (int)(L & 2047);
            size_t br = L >> 11;
            int st  = c >> 6;
            int rem = c & 63;
            int j   = rem >> 3;
            int l0i = (rem & 7) >> 1;
            size_t base = (br * 32 + st) * 64 + j * 2;
            uchar2 a, b2;
            a.x  = (unsigned char)v.x; a.y  = (unsigned char)v.y;
            b2.x = (unsigned char)v.z; b2.y = (unsigned char)v.w;
            *(uchar2*)&g_mask8[base + l0i * 16]       = a;
            *(uchar2*)&g_mask8[base + (l0i + 1) * 16] = b2;
        }
        return;
    }

    const int mode = mode_base + blockIdx.z;
    const __half* Ahi = (mode < 3) ? g_xhi : g_ahi;
    const __half* Alo = (mode < 3) ? g_xlo : g_ahi;    // t2 unused when nch==32
    const __half* Bhi = (mode < 3) ? g_wthi + (size_t)mode * 1048576 : g_wohi;
    const __half* Blo = (mode < 3) ? g_wtlo + (size_t)mode * 1048576 : g_wolo;
    const float* bias = (mode == 0) ? bq : (mode == 1) ? bk : (mode == 2) ? bv : bo;
    const int nch = (mode <= 1) ? 48 : 32;   // 3 terms vs 2 terms

    const int tid = threadIdx.x;
    const int wid = tid >> 5, lane = tid & 31;
    const int m0 = (wid & 3) * 32, n0 = (wid >> 2) * 64;
    const int row0 = blockIdx.y * 128, col0 = blockIdx.x * 128;
    const uint32_t sb = smem_u32(smem);
    const int lrow = lane & 15;
    const int lkof = (lane & 16) >> 1;

    float acc[2][8][4];
#pragma unroll
    for (int i = 0; i < 2; ++i)
#pragma unroll
        for (int j = 0; j < 8; ++j)
#pragma unroll
            for (int c = 0; c < 4; ++c) acc[i][j][c] = 0.f;

    auto issue = [&](int c) {
        int t = c >> 4, k0 = (c & 15) << 6;
        const __half* Ap = (t < 2) ? Ahi : Alo;
        const __half* Bp = (t == 1) ? Blo : Bhi;
        uint32_t dst = sb + (c & 1) * G_STAGE;
#pragma unroll
        for (int it = 0; it < 4; ++it) {
            int idx = it * 256 + tid;
            int r = idx >> 3, k8 = (idx & 7) << 3;
            uint32_t o = swz_h(r, k8);
            CP_A16(dst + o,         Ap + (size_t)(row0 + r) * 1024 + k0 + k8);
            CP_A16(dst + 16384 + o, Bp + (size_t)(col0 + r) * 1024 + k0 + k8);
        }
        CP_COMMIT();
    };

    issue(0);
    for (int c = 0; c < nch; ++c) {
        CP_WAIT0();
        __syncthreads();
        if (c + 1 < nch) issue(c + 1);
        const uint32_t aoff = sb + (c & 1) * G_STAGE;
        const uint32_t boff = aoff + 16384;
#pragma unroll
        for (int kk = 0; kk < 64; kk += 16) {
            uint32_t af[2][4], bf[4][4];
#pragma unroll
            for (int mi = 0; mi < 2; ++mi)
                ldsm_x4(af[mi], aoff + swz_h(m0 + mi * 16 + lrow, kk + lkof));
#pragma unroll
            for (int g = 0; g < 4; ++g)
                ldsm_x4(bf[g], boff + swz_h(n0 + g * 16 + lrow, kk + lkof));
#pragma unroll
            for (int mi = 0; mi < 2; ++mi)
#pragma unroll
                for (int g = 0; g < 4; ++g) {
                    mma16816(acc[mi][2 * g],     af[mi], bf[g][0], bf[g][2]);
                    mma16816(acc[mi][2 * g + 1], af[mi], bf[g][1], bf[g][3]);
                }
        }
    }

    // epilogue
    const int frow = m0 + (lane >> 2);
    const int fcol = n0 + 2 * (lane & 3);
#pragma unroll
    for (int mi = 0; mi < 2; ++mi) {
#pragma unroll
        for (int nj = 0; nj < 8; ++nj) {
            int col = col0 + fcol + nj * 8;
            int r0 = row0 + frow + mi * 16;
            float b0 = bias[col], b1 = bias[col + 1];
            float v0 = acc[mi][nj][0] + b0, v1 = acc[mi][nj][1] + b1;
            float v2 = acc[mi][nj][2] + b0, v3 = acc[mi][nj][3] + b1;
            if (mode == 0) {
                // extra LOG2E folded in so softmax can use raw ex2
                float p0 = pds[col & 63], p1 = pds[(col + 1) & 63];
                float s0 = (LOG2E_ * LOG2E_ * 0.125f) * ((p0 > 20.f) ? p0 : log1pf(__expf(p0)));
                float s1 = (LOG2E_ * LOG2E_ * 0.125f) * ((p1 > 20.f) ? p1 : log1pf(__expf(p1)));
                v0 *= s0; v1 *= s1; v2 *= s0; v3 *= s1;
            }
            if (mode <= 1) {
                __half* Chi = (mode == 0) ? g_qhi : g_khi;
                __half* Clo = (mode == 0) ? g_qlo : g_klo;
                uint32_t h, l;
                split2(v0, v1, h, l);
                *(uint32_t*)&Chi[(size_t)r0 * 1024 + col] = h;
                *(uint32_t*)&Clo[(size_t)r0 * 1024 + col] = l;
                split2(v2, v3, h, l);
                *(uint32_t*)&Chi[(size_t)(r0 + 8) * 1024 + col] = h;
                *(uint32_t*)&Clo[(size_t)(r0 + 8) * 1024 + col] = l;
            } else if (mode == 2) {
                *(uint32_t*)&g_v16[(size_t)r0 * 1024 + col] =
                    pack_h2(__float2half_rn(v0), __float2half_rn(v1));
                *(uint32_t*)&g_v16[(size_t)(r0 + 8) * 1024 + col] =
                    pack_h2(__float2half_rn(v2), __float2half_rn(v3));
            } else {
                *(float2*)&out[(size_t)r0 * 1024 + col] = make_float2(v0, v1);
                *(float2*)&out[(size_t)(r0 + 8) * 1024 + col] = make_float2(v2, v3);
            }
        }
    }
}

// ---------------------------------------------------------------------------
// Flash attention, HMMA. 64 q rows, 128 thr / 4 warps, 2-stage KV ring,
// one sync per tile. Q frags direct from gmem; packed fragment-order mask.
// QK^T 3-term (Kh reuse). Softmax probabilities computed with
// ex2.approx.f16x2 (one MUFU op -> two packed fp16 P values = the PV A-frag).
// Row sums l computed by an extra "ones-column" MMA per kt: constant B-frag
// (no smem), fp32-exact sum of the SAME fp16 p's used in the numerator, and
// rescaled by f each tile along with oacc. One shfl at the end recovers l.
// ---------------------------------------------------------------------------
#define A_KVSTAGE 24576
#define ATTN_SMEM (2 * A_KVSTAGE)   // 49152
__global__ __launch_bounds__(128, 4) void attn_hmma_kernel()
{
    extern __shared__ char smem[];
    const int tid = threadIdx.x;
    const int wid = tid >> 5, lane = tid & 31;
    const int q0 = blockIdx.x * 64;
    const int n  = blockIdx.y;
    const int b  = blockIdx.z;
    const uint32_t sb = smem_u32(smem);
    const int lrow = lane & 15;
    const int lkof = (lane & 16) >> 1;

    auto issue_kv = [&](int st, int stage) {
        size_t gk0 = (size_t)(b * TT + st * 64) * 1024 + n * 64;
        uint32_t base = sb + stage * A_KVSTAGE;
#pragma unroll
        for (int it = 0; it < 4; ++it) {
            int idx = it * 128 + tid;
            int r = idx >> 3, k8 = (idx & 7) << 3;
            size_t g = gk0 + (size_t)r * 1024 + k8;
            uint32_t o = swz_h(r, k8);
            CP_A16(base + o,         g_khi + g);
            CP_A16(base + 8192 + o,  g_klo + g);
            CP_A16(base + 16384 + o, g_v16 + g);
        }
        CP_COMMIT();
    };
    issue_kv(0, 0);

    // ---- Q fragments straight from gmem (m16n8k16 A-frag layout) ----
    const int qrl = q0 + wid * 16 + (lane >> 2);
    const int qc0 = 2 * (lane & 3);
    uint32_t qh[4][4], ql[4][4];
    {
        const size_t qb = (size_t)(b * TT + qrl) * 1024 + n * 64 + qc0;
#pragma unroll
        for (int kt = 0; kt < 4; ++kt) {
            size_t o0 = qb + kt * 16;
            qh[kt][0] = *(const uint32_t*)&g_qhi[o0];
            qh[kt][1] = *(const uint32_t*)&g_qhi[o0 + 8 * 1024];
            qh[kt][2] = *(const uint32_t*)&g_qhi[o0 + 8];
            qh[kt][3] = *(const uint32_t*)&g_qhi[o0 + 8 * 1024 + 8];
            ql[kt][0] = *(const uint32_t*)&g_qlo[o0];
            ql[kt][1] = *(const uint32_t*)&g_qlo[o0 + 8 * 1024];
            ql[kt][2] = *(const uint32_t*)&g_qlo[o0 + 8];
            ql[kt][3] = *(const uint32_t*)&g_qlo[o0 + 8 * 1024 + 8];
        }
    }

    float oacc[8][4];
#pragma unroll
    for (int j = 0; j < 8; ++j)
#pragma unroll
        for (int c = 0; c < 4; ++c) oacc[j][c] = 0.f;
    float lacc[4] = {0.f, 0.f, 0.f, 0.f};            // ones-column accumulator
    float m_0 = -3.0e38f, m_1 = -3.0e38f;

    // ones-matrix B-frag: B[k][n] = (n==0); thread's n = lane>>2
    const uint32_t ones_b = (lane < 4) ? 0x3C003C00u : 0u;

    const unsigned char* mp0 = g_mask8 + ((size_t)(b * TT + qrl) * 32) * 64 + (lane & 3) * 16;

    for (int st = 0; st < TT / 64; ++st) {
        CP_WAIT0();
        __syncthreads();
        if (st + 1 < TT / 64) issue_kv(st + 1, (st + 1) & 1);

        const uint32_t kvb = sb + (st & 1) * A_KVSTAGE;

        // ---- S = QK^T: Kh phase (Qh*Kh + Ql*Kh), then Kl phase (Qh*Kl) ----
        float sacc[8][4];
#pragma unroll
        for (int j = 0; j < 8; ++j)
#pragma unroll
            for (int c = 0; c < 4; ++c) sacc[j][c] = 0.f;
#pragma unroll
        for (int kq = 0; kq < 4; ++kq) {
            uint32_t bf[4][4];
#pragma unroll
            for (int g = 0; g < 4; ++g)
                ldsm_x4(bf[g], kvb + swz_h(g * 16 + lrow, kq * 16 + lkof));
#pragma unroll
            for (int g = 0; g < 4; ++g) {
                mma16816(sacc[2 * g],     qh[kq], bf[g][0], bf[g][2]);
                mma16816(sacc[2 * g + 1], qh[kq], bf[g][1], bf[g][3]);
                mma16816(sacc[2 * g],     ql[kq], bf[g][0], bf[g][2]);
                mma16816(sacc[2 * g + 1], ql[kq], bf[g][1], bf[g][3]);
            }
        }
#pragma unroll
        for (int kq = 0; kq < 4; ++kq) {
            uint32_t bf[4][4];
#pragma unroll
            for (int g = 0; g < 4; ++g)
                ldsm_x4(bf[g], kvb + 8192 + swz_h(g * 16 + lrow, kq * 16 + lkof));
#pragma unroll
            for (int g = 0; g < 4; ++g) {
                mma16816(sacc[2 * g],     qh[kq], bf[g][0], bf[g][2]);
                mma16816(sacc[2 * g + 1], qh[kq], bf[g][1], bf[g][3]);
            }
        }

        // ---- mask: 2x uint4, fragment-order packed ----
        {
            uint4 mA = *(const uint4*)(mp0 + (size_t)st * 64);
            uint4 mB = *(const uint4*)(mp0 + (size_t)st * 64 + 16384);
            uint32_t wA[4] = { mA.x, mA.y, mA.z, mA.w };
            uint32_t wB[4] = { mB.x, mB.y, mB.z, mB.w };
#pragma unroll
            for (int j = 0; j < 8; ++j) {
                uint32_t sA = wA[j >> 1] >> ((j & 1) * 16);
                uint32_t sB = wB[j >> 1] >> ((j & 1) * 16);
                if (!(sA & 0x00ffu)) sacc[j][0] = -1.0e9f;
                if (!(sA & 0xff00u)) sacc[j][1] = -1.0e9f;
                if (!(sB & 0x00ffu)) sacc[j][2] = -1.0e9f;
                if (!(sB & 0xff00u)) sacc[j][3] = -1.0e9f;
            }
        }

        // ---- online max (log2 domain) ----
        float mx0 = -3.0e38f, mx1 = -3.0e38f;
#pragma unroll
        for (int j = 0; j < 8; ++j) {
            mx0 = fmaxf(mx0, fmaxf(sacc[j][0], sacc[j][1]));
            mx1 = fmaxf(mx1, fmaxf(sacc[j][2], sacc[j][3]));
        }
        mx0 = fmaxf(mx0, __shfl_xor_sync(0xffffffffu, mx0, 1));
        mx0 = fmaxf(mx0, __shfl_xor_sync(0xffffffffu, mx0, 2));
        mx1 = fmaxf(mx1, __shfl_xor_sync(0xffffffffu, mx1, 1));
        mx1 = fmaxf(mx1, __shfl_xor_sync(0xffffffffu, mx1, 2));
        float mn0 = fmaxf(m_0, mx0), mn1 = fmaxf(m_1, mx1);
        float f0 = ex2(m_0 - mn0), f1 = ex2(m_1 - mn1);
        m_0 = mn0; m_1 = mn1;
#pragma unroll
        for (int j = 0; j < 8; ++j) {
            oacc[j][0] *= f0; oacc[j][1] *= f0;
            oacc[j][2] *= f1; oacc[j][3] *= f1;
        }
        lacc[0] *= f0; lacc[2] *= f1;

        // ---- P in fp16 via ex2.f16x2, then O += P V and l += P * ones ----
#pragma unroll
        for (int kt = 0; kt < 4; ++kt) {
            uint32_t ph[4];
            {
                const float* sA = sacc[2 * kt];
                const float* sB = sacc[2 * kt + 1];
                ph[0] = ex2h2(sA[0] - mn0, sA[1] - mn0);
                ph[1] = ex2h2(sA[2] - mn1, sA[3] - mn1);
                ph[2] = ex2h2(sB[0] - mn0, sB[1] - mn0);
                ph[3] = ex2h2(sB[2] - mn1, sB[3] - mn1);
            }
            uint32_t vf[4][4];
#pragma unroll
            for (int g = 0; g < 4; ++g)
                ldsm_x4_t(vf[g], kvb + 16384 + swz_h(kt * 16 + lrow, g * 16 + lkof));
#pragma unroll
            for (int g = 0; g < 4; ++g) {
                mma16816(oacc[2 * g],     ph, vf[g][0], vf[g][1]);
                mma16816(oacc[2 * g + 1], ph, vf[g][2], vf[g][3]);
            }
            mma16816(lacc, ph, ones_b, ones_b);
        }
        // no tail sync: next iteration's top sync covers the stage overwrite
    }

    // ---- recover row sums, normalize, fp16 store (hi only) ----
    const float ls0 = __shfl_sync(0xffffffffu, lacc[0], lane & ~3);
    const float ls1 = __shfl_sync(0xffffffffu, lacc[2], lane & ~3);
    const float inv0 = 1.0f / ls0, inv1 = 1.0f / ls1;
    const size_t m_lo = (size_t)(b * TT + qrl) * 1024 + n * 64;
#pragma unroll
    for (int j = 0; j < 8; ++j) {
        int col = j * 8 + qc0;
        *(uint32_t*)&g_ahi[m_lo + col] =
            pack_h2(__float2half_rn(oacc[j][0] * inv0), __float2half_rn(oacc[j][1] * inv0));
        *(uint32_t*)&g_ahi[m_lo + 8 * 1024 + col] =
            pack_h2(__float2half_rn(oacc[j][2] * inv1), __float2half_rn(oacc[j][3] * inv1));
    }
}

// ---------------------------------------------------------------------------
// Launch
// ---------------------------------------------------------------------------
extern "C" void kernel_launch(void* const* d_in, const int* in_sizes, int n_in,
                              void* d_out, int out_size)
{
    const float* x    = (const float*)d_in[0];
    const int*   mask = (const int*)  d_in[1];
    const float* wq   = (const float*)d_in[2];
    const float* bq   = (const float*)d_in[3];
    const float* wk   = (const float*)d_in[4];
    const float* bk   = (const float*)d_in[5];
    const float* wv   = (const float*)d_in[6];
    const float* bv   = (const float*)d_in[7];
    const float* wo   = (const float*)d_in[8];
    const float* bo   = (const float*)d_in[9];
    const float* pds  = (const float*)d_in[10];
    float* out = (float*)d_out;

    cudaFuncSetAttribute(gemm_split_kernel, cudaFuncAttributeMaxDynamicSharedMemorySize, GEMM_SMEM);
    cudaFuncSetAttribute(attn_hmma_kernel, cudaFuncAttributeMaxDynamicSharedMemorySize, ATTN_SMEM);

    split_x_kernel<<<4096, 256>>>(x);
    transpose_split_kernel<<<dim3(32, 32, 3), dim3(32, 8)>>>(wq, wk, wv);

    // z = 0..2: Q/K/V GEMMs; z = 3: aux slice (wo split + mask packing)
    gemm_split_kernel<<<dim3(8, 32, 4), 256, GEMM_SMEM>>>(bq, bk, bv, bo, pds, wo, mask, out, 0);
    attn_hmma_kernel<<<dim3(32, 16, 2), 128, ATTN_SMEM>>>();
    gemm_split_kernel<<<dim3(8, 32, 1), 256, GEMM_SMEM>>>(bq, bk, bv, bo, pds, wo, mask, out, 3);
}

// round 17
// speedup vs baseline: 1.5430x; 1.5430x over previous
#include <cuda_runtime.h>
#include <cuda_fp16.h>
#include <math.h>
#include <cstdint>

#define BB 2
#define TT 2048
#define DD 1024
#define NH 16
#define HD 64
#define LOG2E_ 1.442695041f

// ---------------------------------------------------------------------------
// Scratch (__device__ globals, allocation-free rule)
// ---------------------------------------------------------------------------
__device__ __half g_xhi[4194304], g_xlo[4194304];        // X split       [4096][1024]
__device__ __half g_wthi[3145728], g_wtlo[3145728];      // wq/wk/wv^T    [3][1024 n][1024 k]
__device__ __half g_wohi[1048576], g_wolo[1048576];      // wo split      [1024 d][1024 k]
__device__ __half g_qhi[4194304], g_qlo[4194304];        // q (scaled)    [4096][1024]
__device__ __half g_khi[4194304], g_klo[4194304];        // k             [4096][1024]
__device__ __half g_v16[4194304];                        // v fp16        [4096][1024]
__device__ __half g_ahi[4194304];                        // attn out hi   [4096][1024]
// mask packed in fragment order: [b][row][st][l(4)][j(8)][p(2)] (8MB)
__device__ unsigned char g_mask8[8388608];

// ---------------------------------------------------------------------------
// PTX helpers
// ---------------------------------------------------------------------------
__device__ __forceinline__ uint32_t smem_u32(const void* p) {
    uint32_t a;
    asm("{ .reg .u64 t; cvta.to.shared.u64 t, %1; cvt.u32.u64 %0, t; }" : "=r"(a) : "l"(p));
    return a;
}
__device__ __forceinline__ void ldsm_x4(uint32_t* r, uint32_t a) {
    asm volatile("ldmatrix.sync.aligned.m8n8.x4.shared.b16 {%0,%1,%2,%3}, [%4];"
                 : "=r"(r[0]), "=r"(r[1]), "=r"(r[2]), "=r"(r[3]) : "r"(a));
}
__device__ __forceinline__ void ldsm_x4_t(uint32_t* r, uint32_t a) {
    asm volatile("ldmatrix.sync.aligned.m8n8.x4.trans.shared.b16 {%0,%1,%2,%3}, [%4];"
                 : "=r"(r[0]), "=r"(r[1]), "=r"(r[2]), "=r"(r[3]) : "r"(a));
}
__device__ __forceinline__ void mma16816(float* c, const uint32_t* a, uint32_t b0, uint32_t b1) {
    asm volatile(
        "mma.sync.aligned.m16n8k16.row.col.f32.f16.f16.f32 "
        "{%0,%1,%2,%3}, {%4,%5,%6,%7}, {%8,%9}, {%0,%1,%2,%3};"
        : "+f"(c[0]), "+f"(c[1]), "+f"(c[2]), "+f"(c[3])
        : "r"(a[0]), "r"(a[1]), "r"(a[2]), "r"(a[3]), "r"(b0), "r"(b1));
}
#define CP_A16(dst, src) \
    asm volatile("cp.async.cg.shared.global [%0], [%1], 16;" :: "r"(dst), "l"(src))
#define CP_COMMIT() asm volatile("cp.async.commit_group;" ::: "memory")
#define CP_WAIT0()  asm volatile("cp.async.wait_group 0;" ::: "memory")

__device__ __forceinline__ float ex2(float x) {
    float y;
    asm("ex2.approx.ftz.f32 %0, %1;" : "=f"(y) : "f"(x));
    return y;
}

// swizzled byte offset, 64-half (128B) rows
__device__ __forceinline__ uint32_t swz_h(int r, int k) {
    return (uint32_t)(r * 128 + (((k >> 3) ^ (r & 7)) << 4) + ((k & 7) << 1));
}
__device__ __forceinline__ uint32_t pack_h2(__half a, __half b) {
    __half2 h = __halves2half2(a, b);
    return *(uint32_t*)&h;
}
__device__ __forceinline__ void split2(float x, float y, uint32_t& hi, uint32_t& lo) {
    __half hx = __float2half_rn(x), hy = __float2half_rn(y);
    hi = pack_h2(hx, hy);
    lo = pack_h2(__float2half_rn(x - __half2float(hx)),
                 __float2half_rn(y - __half2float(hy)));
}

// ---------------------------------------------------------------------------
// Merged preprocess: blocks [0,3072) = weight transpose+split (wq/wk/wv),
// blocks [3072,7168) = X split. One launch, 256 threads each.
// ---------------------------------------------------------------------------
__global__ __launch_bounds__(256) void preprocess_kernel(
    const float* __restrict__ x,
    const float* __restrict__ wq, const float* __restrict__ wk, const float* __restrict__ wv)
{
    __shared__ float t[32][33];
    const int bi = blockIdx.x;
    const int tid = threadIdx.x;

    if (bi < 3072) {
        const int z = bi >> 10;                 // 0..2
        const int by = (bi >> 5) & 31;          // n block
        const int bx = bi & 31;                 // k block
        const float* src = (z == 0) ? wq : (z == 1) ? wk : wv;
        __half* dhi = g_wthi + (size_t)z * 1048576;
        __half* dlo = g_wtlo + (size_t)z * 1048576;
        const int tx = tid & 31, ty = tid >> 5;   // 32 x 8
        const int x0 = bx * 32;  // k
        const int y0 = by * 32;  // n
#pragma unroll
        for (int i = 0; i < 4; ++i)
            t[ty + i * 8][tx] = src[(size_t)(x0 + ty + i * 8) * 1024 + y0 + tx];
        __syncthreads();
#pragma unroll
        for (int i = 0; i < 4; ++i) {
            float v = t[tx][ty + i * 8];
            __half h = __float2half_rn(v);
            dhi[(size_t)(y0 + ty + i * 8) * 1024 + x0 + tx] = h;
            dlo[(size_t)(y0 + ty + i * 8) * 1024 + x0 + tx] =
                __float2half_rn(v - __half2float(h));
        }
    } else {
        int i = (bi - 3072) * 256 + tid;
        float4 v = *(const float4*)&x[(size_t)i * 4];
        uint32_t h0, l0, h1, l1;
        split2(v.x, v.y, h0, l0);
        split2(v.z, v.w, h1, l1);
        *(uint32_t*)&g_xhi[(size_t)i * 4] = h0; *(uint32_t*)&g_xhi[(size_t)i * 4 + 2] = h1;
        *(uint32_t*)&g_xlo[(size_t)i * 4] = l0; *(uint32_t*)&g_xlo[(size_t)i * 4 + 2] = l1;
    }
}

// ---------------------------------------------------------------------------
// Split-fp16 HMMA GEMM (R15 config, unchanged): C = A @ B^T + bias.
// 2-stage ring, one sync per chunk; z==3 aux slice on the qkv launch.
// ---------------------------------------------------------------------------
#define G_STAGE 32768              // A 16KB + B 16KB per stage
#define GEMM_SMEM (2 * G_STAGE)    // 65536
__global__ __launch_bounds__(256, 2) void gemm_split_kernel(
    const float* __restrict__ bq, const float* __restrict__ bk,
    const float* __restrict__ bv, const float* __restrict__ bo,
    const float* __restrict__ pds, const float* __restrict__ wo,
    const int* __restrict__ msk, float* __restrict__ out, int mode_base)
{
    extern __shared__ char smem[];

    // ---- AUX slice (qkv launch only): wo split + mask packing ----
    if (mode_base == 0 && blockIdx.z == 3) {
        int t0 = (blockIdx.y * 8 + blockIdx.x) * 256 + threadIdx.x;  // 0..65535
        for (int i = t0; i < 262144; i += 65536) {                   // wo: 262144 float4
            float4 v = *(const float4*)&wo[(size_t)i * 4];
            uint32_t h0, l0, h1, l1;
            split2(v.x, v.y, h0, l0);
            split2(v.z, v.w, h1, l1);
            *(uint32_t*)&g_wohi[(size_t)i * 4] = h0; *(uint32_t*)&g_wohi[(size_t)i * 4 + 2] = h1;
            *(uint32_t*)&g_wolo[(size_t)i * 4] = l0; *(uint32_t*)&g_wolo[(size_t)i * 4 + 2] = l1;
        }
        for (int i = t0; i < 2097152; i += 65536) {                  // mask: 2097152 int4
            size_t L = (size_t)i * 4;
            int4 v = *(const int4*)&msk[L];
            int c   = (int)(L & 2047);
            size_t br = L >> 11;
            int st  = c >> 6;
            int rem = c & 63;
            int j   = rem >> 3;
            int l0i = (rem & 7) >> 1;
            size_t base = (br * 32 + st) * 64 + j * 2;
            uchar2 a, b2;
            a.x  = (unsigned char)v.x; a.y  = (unsigned char)v.y;
            b2.x = (unsigned char)v.z; b2.y = (unsigned char)v.w;
            *(uchar2*)&g_mask8[base + l0i * 16]       = a;
            *(uchar2*)&g_mask8[base + (l0i + 1) * 16] = b2;
        }
        return;
    }

    const int mode = mode_base + blockIdx.z;
    const __half* Ahi = (mode < 3) ? g_xhi : g_ahi;
    const __half* Alo = (mode < 3) ? g_xlo : g_ahi;    // t2 unused when nch==32
    const __half* Bhi = (mode < 3) ? g_wthi + (size_t)mode * 1048576 : g_wohi;
    const __half* Blo = (mode < 3) ? g_wtlo + (size_t)mode * 1048576 : g_wolo;
    const float* bias = (mode == 0) ? bq : (mode == 1) ? bk : (mode == 2) ? bv : bo;
    const int nch = (mode <= 1) ? 48 : 32;   // 3 terms vs 2 terms

    const int tid = threadIdx.x;
    const int wid = tid >> 5, lane = tid & 31;
    const int m0 = (wid & 3) * 32, n0 = (wid >> 2) * 64;
    const int row0 = blockIdx.y * 128, col0 = blockIdx.x * 128;
    const uint32_t sb = smem_u32(smem);
    const int lrow = lane & 15;
    const int lkof = (lane & 16) >> 1;

    float acc[2][8][4];
#pragma unroll
    for (int i = 0; i < 2; ++i)
#pragma unroll
        for (int j = 0; j < 8; ++j)
#pragma unroll
            for (int c = 0; c < 4; ++c) acc[i][j][c] = 0.f;

    auto issue = [&](int c) {
        int t = c >> 4, k0 = (c & 15) << 6;
        const __half* Ap = (t < 2) ? Ahi : Alo;
        const __half* Bp = (t == 1) ? Blo : Bhi;
        uint32_t dst = sb + (c & 1) * G_STAGE;
#pragma unroll
        for (int it = 0; it < 4; ++it) {
            int idx = it * 256 + tid;
            int r = idx >> 3, k8 = (idx & 7) << 3;
            uint32_t o = swz_h(r, k8);
            CP_A16(dst + o,         Ap + (size_t)(row0 + r) * 1024 + k0 + k8);
            CP_A16(dst + 16384 + o, Bp + (size_t)(col0 + r) * 1024 + k0 + k8);
        }
        CP_COMMIT();
    };

    issue(0);
    for (int c = 0; c < nch; ++c) {
        CP_WAIT0();
        __syncthreads();
        if (c + 1 < nch) issue(c + 1);
        const uint32_t aoff = sb + (c & 1) * G_STAGE;
        const uint32_t boff = aoff + 16384;
#pragma unroll
        for (int kk = 0; kk < 64; kk += 16) {
            uint32_t af[2][4], bf[4][4];
#pragma unroll
            for (int mi = 0; mi < 2; ++mi)
                ldsm_x4(af[mi], aoff + swz_h(m0 + mi * 16 + lrow, kk + lkof));
#pragma unroll
            for (int g = 0; g < 4; ++g)
                ldsm_x4(bf[g], boff + swz_h(n0 + g * 16 + lrow, kk + lkof));
#pragma unroll
            for (int mi = 0; mi < 2; ++mi)
#pragma unroll
                for (int g = 0; g < 4; ++g) {
                    mma16816(acc[mi][2 * g],     af[mi], bf[g][0], bf[g][2]);
                    mma16816(acc[mi][2 * g + 1], af[mi], bf[g][1], bf[g][3]);
                }
        }
    }

    // epilogue
    const int frow = m0 + (lane >> 2);
    const int fcol = n0 + 2 * (lane & 3);
#pragma unroll
    for (int mi = 0; mi < 2; ++mi) {
#pragma unroll
        for (int nj = 0; nj < 8; ++nj) {
            int col = col0 + fcol + nj * 8;
            int r0 = row0 + frow + mi * 16;
            float b0 = bias[col], b1 = bias[col + 1];
            float v0 = acc[mi][nj][0] + b0, v1 = acc[mi][nj][1] + b1;
            float v2 = acc[mi][nj][2] + b0, v3 = acc[mi][nj][3] + b1;
            if (mode == 0) {
                // extra LOG2E folded in so softmax can use raw ex2
                float p0 = pds[col & 63], p1 = pds[(col + 1) & 63];
                float s0 = (LOG2E_ * LOG2E_ * 0.125f) * ((p0 > 20.f) ? p0 : log1pf(__expf(p0)));
                float s1 = (LOG2E_ * LOG2E_ * 0.125f) * ((p1 > 20.f) ? p1 : log1pf(__expf(p1)));
                v0 *= s0; v1 *= s1; v2 *= s0; v3 *= s1;
            }
            if (mode <= 1) {
                __half* Chi = (mode == 0) ? g_qhi : g_khi;
                __half* Clo = (mode == 0) ? g_qlo : g_klo;
                uint32_t h, l;
                split2(v0, v1, h, l);
                *(uint32_t*)&Chi[(size_t)r0 * 1024 + col] = h;
                *(uint32_t*)&Clo[(size_t)r0 * 1024 + col] = l;
                split2(v2, v3, h, l);
                *(uint32_t*)&Chi[(size_t)(r0 + 8) * 1024 + col] = h;
                *(uint32_t*)&Clo[(size_t)(r0 + 8) * 1024 + col] = l;
            } else if (mode == 2) {
                *(uint32_t*)&g_v16[(size_t)r0 * 1024 + col] =
                    pack_h2(__float2half_rn(v0), __float2half_rn(v1));
                *(uint32_t*)&g_v16[(size_t)(r0 + 8) * 1024 + col] =
                    pack_h2(__float2half_rn(v2), __float2half_rn(v3));
            } else {
                *(float2*)&out[(size_t)r0 * 1024 + col] = make_float2(v0, v1);
                *(float2*)&out[(size_t)(r0 + 8) * 1024 + col] = make_float2(v2, v3);
            }
        }
    }
}

// ---------------------------------------------------------------------------
// Flash attention, HMMA (R15-proven config, exact revert). 64 q rows,
// 128 thr / 4 warps, 2-stage KV ring, one sync per tile. Q frags direct from
// gmem; packed fragment-order mask. QK^T 3-term (Kh reuse); PV single-term
// fp16 P; fp32 ex2 softmax; fp16 hi-only output.
// ---------------------------------------------------------------------------
#define A_KVSTAGE 24576
#define ATTN_SMEM (2 * A_KVSTAGE)   // 49152
__global__ __launch_bounds__(128, 4) void attn_hmma_kernel()
{
    extern __shared__ char smem[];
    const int tid = threadIdx.x;
    const int wid = tid >> 5, lane = tid & 31;
    const int q0 = blockIdx.x * 64;
    const int n  = blockIdx.y;
    const int b  = blockIdx.z;
    const uint32_t sb = smem_u32(smem);
    const int lrow = lane & 15;
    const int lkof = (lane & 16) >> 1;

    auto issue_kv = [&](int st, int stage) {
        size_t gk0 = (size_t)(b * TT + st * 64) * 1024 + n * 64;
        uint32_t base = sb + stage * A_KVSTAGE;
#pragma unroll
        for (int it = 0; it < 4; ++it) {
            int idx = it * 128 + tid;
            int r = idx >> 3, k8 = (idx & 7) << 3;
            size_t g = gk0 + (size_t)r * 1024 + k8;
            uint32_t o = swz_h(r, k8);
            CP_A16(base + o,         g_khi + g);
            CP_A16(base + 8192 + o,  g_klo + g);
            CP_A16(base + 16384 + o, g_v16 + g);
        }
        CP_COMMIT();
    };
    issue_kv(0, 0);

    // ---- Q fragments straight from gmem (m16n8k16 A-frag layout) ----
    const int qrl = q0 + wid * 16 + (lane >> 2);
    const int qc0 = 2 * (lane & 3);
    uint32_t qh[4][4], ql[4][4];
    {
        const size_t qb = (size_t)(b * TT + qrl) * 1024 + n * 64 + qc0;
#pragma unroll
        for (int kt = 0; kt < 4; ++kt) {
            size_t o0 = qb + kt * 16;
            qh[kt][0] = *(const uint32_t*)&g_qhi[o0];
            qh[kt][1] = *(const uint32_t*)&g_qhi[o0 + 8 * 1024];
            qh[kt][2] = *(const uint32_t*)&g_qhi[o0 + 8];
            qh[kt][3] = *(const uint32_t*)&g_qhi[o0 + 8 * 1024 + 8];
            ql[kt][0] = *(const uint32_t*)&g_qlo[o0];
            ql[kt][1] = *(const uint32_t*)&g_qlo[o0 + 8 * 1024];
            ql[kt][2] = *(const uint32_t*)&g_qlo[o0 + 8];
            ql[kt][3] = *(const uint32_t*)&g_qlo[o0 + 8 * 1024 + 8];
        }
    }

    float oacc[8][4];
#pragma unroll
    for (int j = 0; j < 8; ++j)
#pragma unroll
        for (int c = 0; c < 4; ++c) oacc[j][c] = 0.f;
    float m_0 = -3.0e38f, m_1 = -3.0e38f, l_0 = 0.f, l_1 = 0.f;

    const unsigned char* mp0 = g_mask8 + ((size_t)(b * TT + qrl) * 32) * 64 + (lane & 3) * 16;

    for (int st = 0; st < TT / 64; ++st) {
        CP_WAIT0();
        __syncthreads();
        if (st + 1 < TT / 64) issue_kv(st + 1, (st + 1) & 1);

        const uint32_t kvb = sb + (st & 1) * A_KVSTAGE;

        // ---- S = QK^T: Kh phase (Qh*Kh + Ql*Kh), then Kl phase (Qh*Kl) ----
        float sacc[8][4];
#pragma unroll
        for (int j = 0; j < 8; ++j)
#pragma unroll
            for (int c = 0; c < 4; ++c) sacc[j][c] = 0.f;
#pragma unroll
        for (int kq = 0; kq < 4; ++kq) {
            uint32_t bf[4][4];
#pragma unroll
            for (int g = 0; g < 4; ++g)
                ldsm_x4(bf[g], kvb + swz_h(g * 16 + lrow, kq * 16 + lkof));
#pragma unroll
            for (int g = 0; g < 4; ++g) {
                mma16816(sacc[2 * g],     qh[kq], bf[g][0], bf[g][2]);
                mma16816(sacc[2 * g + 1], qh[kq], bf[g][1], bf[g][3]);
                mma16816(sacc[2 * g],     ql[kq], bf[g][0], bf[g][2]);
                mma16816(sacc[2 * g + 1], ql[kq], bf[g][1], bf[g][3]);
            }
        }
#pragma unroll
        for (int kq = 0; kq < 4; ++kq) {
            uint32_t bf[4][4];
#pragma unroll
            for (int g = 0; g < 4; ++g)
                ldsm_x4(bf[g], kvb + 8192 + swz_h(g * 16 + lrow, kq * 16 + lkof));
#pragma unroll
            for (int g = 0; g < 4; ++g) {
                mma16816(sacc[2 * g],     qh[kq], bf[g][0], bf[g][2]);
                mma16816(sacc[2 * g + 1], qh[kq], bf[g][1], bf[g][3]);
            }
        }

        // ---- mask: 2x uint4, fragment-order packed ----
        {
            uint4 mA = *(const uint4*)(mp0 + (size_t)st * 64);
            uint4 mB = *(const uint4*)(mp0 + (size_t)st * 64 + 16384);
            uint32_t wA[4] = { mA.x, mA.y, mA.z, mA.w };
            uint32_t wB[4] = { mB.x, mB.y, mB.z, mB.w };
#pragma unroll
            for (int j = 0; j < 8; ++j) {
                uint32_t sA = wA[j >> 1] >> ((j & 1) * 16);
                uint32_t sB = wB[j >> 1] >> ((j & 1) * 16);
                if (!(sA & 0x00ffu)) sacc[j][0] = -1.0e9f;
                if (!(sA & 0xff00u)) sacc[j][1] = -1.0e9f;
                if (!(sB & 0x00ffu)) sacc[j][2] = -1.0e9f;
                if (!(sB & 0xff00u)) sacc[j][3] = -1.0e9f;
            }
        }

        // ---- online softmax (log2 domain, fp32 ex2) ----
        float mx0 = -3.0e38f, mx1 = -3.0e38f;
#pragma unroll
        for (int j = 0; j < 8; ++j) {
            mx0 = fmaxf(mx0, fmaxf(sacc[j][0], sacc[j][1]));
            mx1 = fmaxf(mx1, fmaxf(sacc[j][2], sacc[j][3]));
        }
        mx0 = fmaxf(mx0, __shfl_xor_sync(0xffffffffu, mx0, 1));
        mx0 = fmaxf(mx0, __shfl_xor_sync(0xffffffffu, mx0, 2));
        mx1 = fmaxf(mx1, __shfl_xor_sync(0xffffffffu, mx1, 1));
        mx1 = fmaxf(mx1, __shfl_xor_sync(0xffffffffu, mx1, 2));
        float mn0 = fmaxf(m_0, mx0), mn1 = fmaxf(m_1, mx1);
        float f0 = ex2(m_0 - mn0), f1 = ex2(m_1 - mn1);
        m_0 = mn0; m_1 = mn1;
        float rs0 = 0.f, rs1 = 0.f;
#pragma unroll
        for (int j = 0; j < 8; ++j) {
            sacc[j][0] = ex2(sacc[j][0] - mn0);
            sacc[j][1] = ex2(sacc[j][1] - mn0);
            sacc[j][2] = ex2(sacc[j][2] - mn1);
            sacc[j][3] = ex2(sacc[j][3] - mn1);
            rs0 += sacc[j][0] + sacc[j][1];
            rs1 += sacc[j][2] + sacc[j][3];
        }
        rs0 += __shfl_xor_sync(0xffffffffu, rs0, 1);
        rs0 += __shfl_xor_sync(0xffffffffu, rs0, 2);
        rs1 += __shfl_xor_sync(0xffffffffu, rs1, 1);
        rs1 += __shfl_xor_sync(0xffffffffu, rs1, 2);
        l_0 = l_0 * f0 + rs0;
        l_1 = l_1 * f1 + rs1;
#pragma unroll
        for (int j = 0; j < 8; ++j) {
            oacc[j][0] *= f0; oacc[j][1] *= f0;
            oacc[j][2] *= f1; oacc[j][3] *= f1;
        }

        // ---- O += P V (single-term fp16 P, fp16 V) ----
#pragma unroll
        for (int kt = 0; kt < 4; ++kt) {
            uint32_t ph[4];
            {
                const float* sA = sacc[2 * kt];
                const float* sB = sacc[2 * kt + 1];
                ph[0] = pack_h2(__float2half_rn(sA[0]), __float2half_rn(sA[1]));
                ph[1] = pack_h2(__float2half_rn(sA[2]), __float2half_rn(sA[3]));
                ph[2] = pack_h2(__float2half_rn(sB[0]), __float2half_rn(sB[1]));
                ph[3] = pack_h2(__float2half_rn(sB[2]), __float2half_rn(sB[3]));
            }
            uint32_t vf[4][4];
#pragma unroll
            for (int g = 0; g < 4; ++g)
                ldsm_x4_t(vf[g], kvb + 16384 + swz_h(kt * 16 + lrow, g * 16 + lkof));
#pragma unroll
            for (int g = 0; g < 4; ++g) {
                mma16816(oacc[2 * g],     ph, vf[g][0], vf[g][1]);
                mma16816(oacc[2 * g + 1], ph, vf[g][2], vf[g][3]);
            }
        }
        // no tail sync: next iteration's top sync covers the stage overwrite
    }

    // ---- epilogue: normalize + fp16 store (hi only) ----
    const float inv0 = 1.0f / l_0, inv1 = 1.0f / l_1;
    const size_t m_lo = (size_t)(b * TT + qrl) * 1024 + n * 64;
#pragma unroll
    for (int j = 0; j < 8; ++j) {
        int col = j * 8 + qc0;
        *(uint32_t*)&g_ahi[m_lo + col] =
            pack_h2(__float2half_rn(oacc[j][0] * inv0), __float2half_rn(oacc[j][1] * inv0));
        *(uint32_t*)&g_ahi[m_lo + 8 * 1024 + col] =
            pack_h2(__float2half_rn(oacc[j][2] * inv1), __float2half_rn(oacc[j][3] * inv1));
    }
}

// ---------------------------------------------------------------------------
// Launch
// ---------------------------------------------------------------------------
extern "C" void kernel_launch(void* const* d_in, const int* in_sizes, int n_in,
                              void* d_out, int out_size)
{
    const float* x    = (const float*)d_in[0];
    const int*   mask = (const int*)  d_in[1];
    const float* wq   = (const float*)d_in[2];
    const float* bq   = (const float*)d_in[3];
    const float* wk   = (const float*)d_in[4];
    const float* bk   = (const float*)d_in[5];
    const float* wv   = (const float*)d_in[6];
    const float* bv   = (const float*)d_in[7];
    const float* wo   = (const float*)d_in[8];
    const float* bo   = (const float*)d_in[9];
    const float* pds  = (const float*)d_in[10];
    float* out = (float*)d_out;

    cudaFuncSetAttribute(gemm_split_kernel, cudaFuncAttributeMaxDynamicSharedMemorySize, GEMM_SMEM);
    cudaFuncSetAttribute(attn_hmma_kernel, cudaFuncAttributeMaxDynamicSharedMemorySize, ATTN_SMEM);

    preprocess_kernel<<<7168, 256>>>(x, wq, wk, wv);

    // z = 0..2: Q/K/V GEMMs; z = 3: aux slice (wo split + mask packing)
    gemm_split_kernel<<<dim3(8, 32, 4), 256, GEMM_SMEM>>>(bq, bk, bv, bo, pds, wo, mask, out, 0);
    attn_hmma_kernel<<<dim3(32, 16, 2), 128, ATTN_SMEM>>>();
    gemm_split_kernel<<<dim3(8, 32, 1), 256, GEMM_SMEM>>>(bq, bk, bv, bo, pds, wo, mask, out, 3);
}